// round 4
// baseline (speedup 1.0000x reference)
#include <cuda_runtime.h>
#include <math.h>

#define MAXN 100000
#define MAXE 1600000
#define NBLK 98          // ceil(MAXN/1024) for scans

typedef unsigned long long u64;

// ---- packed f32x2 helpers (sm_100+: one issue slot = 2 fp32 FMAs) ----------
__device__ __forceinline__ u64 bcast2(float v) {
    u64 r; asm("mov.b64 %0, {%1, %1};" : "=l"(r) : "f"(v)); return r;
}
__device__ __forceinline__ void ffma2(u64& d, u64 a, u64 b) {
    asm("fma.rn.f32x2 %0, %1, %2, %0;" : "+l"(d) : "l"(a), "l"(b));
}
__device__ __forceinline__ void unpack2(float& lo, float& hi, u64 v) {
    asm("mov.b64 {%0, %1}, %2;" : "=f"(lo), "=f"(hi) : "l"(v));
}

// Scratch (__device__ globals; no allocation allowed)
__device__ float  g_h[(size_t)MAXN * 128];    // h = x @ W (per layer)
__device__ float  g_agg[(size_t)MAXN * 128];  // aggregated layer-1 output
__device__ float  g_g1[MAXE];                 // edge gates layer 1
__device__ float  g_g2[MAXE];                 // edge gates layer 2
__device__ float  g_d1[MAXN];                 // deg -> rsqrt(deg) layer 1
__device__ float  g_d2[MAXN];                 // deg -> rsqrt(deg) layer 2
__device__ int    g_cnt[MAXN];                // in-degree counts
__device__ int    g_cur[MAXN];                // placement cursors
__device__ int    g_base[MAXN];               // CSR base offsets
__device__ int    g_bsums[NBLK + 1];          // scan block sums
__device__ float4 g_edges[MAXE];              // CSR slot: {row(bits), w1, w2, 0}

// ---------------------------------------------------------------------------
__global__ void init_kernel(float* d1, float* d2, int* cnt, int* cur, int n) {
    int i = blockIdx.x * blockDim.x + threadIdx.x;
    if (i < n) { d1[i] = 1.0f; d2[i] = 1.0f; cnt[i] = 0; cur[i] = 0; }
}

// ---------------------------------------------------------------------------
// Edge gate MLPs for BOTH layers in one pass (f32x2 packed math);
// also weighted in-degree and count histogram (for CSR).
__global__ void __launch_bounds__(256) gate_kernel(
    const float* __restrict__ ea,
    const float* __restrict__ w1a, const float* __restrict__ b1a,
    const float* __restrict__ w2a, const float* __restrict__ b2a,
    const float* __restrict__ w1b, const float* __restrict__ b1b,
    const float* __restrict__ w2b, const float* __restrict__ b2b,
    const int* __restrict__ cols,
    float* __restrict__ g1, float* __restrict__ g2,
    float* __restrict__ deg1, float* __restrict__ deg2,
    int* __restrict__ cnt, int E)
{
    __shared__ __align__(16) float s1[16 * 128];
    __shared__ __align__(16) float s2[16 * 128];
    __shared__ __align__(16) float sb1[128], sb2[128], sv1[128], sv2[128];

    int tid = threadIdx.x;
    for (int i = tid; i < 2048; i += blockDim.x) { s1[i] = w1a[i]; s2[i] = w1b[i]; }
    if (tid < 128) {
        sb1[tid] = b1a[tid]; sb2[tid] = b1b[tid];
        sv1[tid] = w2a[tid]; sv2[tid] = w2b[tid];
    }
    __syncthreads();

    int e = blockIdx.x * blockDim.x + tid;
    if (e >= E) return;

    // load 16 edge attrs, pack each as a broadcast f32x2 pair
    u64 aa[16];
    {
        const float4* p = (const float4*)(ea + (size_t)e * 16);
        float4 q0 = p[0], q1 = p[1], q2 = p[2], q3 = p[3];
        aa[0]  = bcast2(q0.x); aa[1]  = bcast2(q0.y); aa[2]  = bcast2(q0.z); aa[3]  = bcast2(q0.w);
        aa[4]  = bcast2(q1.x); aa[5]  = bcast2(q1.y); aa[6]  = bcast2(q1.z); aa[7]  = bcast2(q1.w);
        aa[8]  = bcast2(q2.x); aa[9]  = bcast2(q2.y); aa[10] = bcast2(q2.z); aa[11] = bcast2(q2.w);
        aa[12] = bcast2(q3.x); aa[13] = bcast2(q3.y); aa[14] = bcast2(q3.z); aa[15] = bcast2(q3.w);
    }

    float acc1 = b2a[0];
    float acc2 = b2b[0];

    #pragma unroll 1
    for (int j = 0; j < 128; j += 4) {
        // hidden accumulators for 4 cols = 2 packed pairs per layer, init = bias
        ulonglong2 hb1 = *(const ulonglong2*)(sb1 + j);
        ulonglong2 hb2 = *(const ulonglong2*)(sb2 + j);
        u64 h1a = hb1.x, h1b = hb1.y;
        u64 h2a = hb2.x, h2b = hb2.y;

        #pragma unroll
        for (int k = 0; k < 16; k++) {
            ulonglong2 w = *(const ulonglong2*)(s1 + k * 128 + j);   // LDS.128
            ffma2(h1a, aa[k], w.x);
            ffma2(h1b, aa[k], w.y);
        }
        #pragma unroll
        for (int k = 0; k < 16; k++) {
            ulonglong2 w = *(const ulonglong2*)(s2 + k * 128 + j);
            ffma2(h2a, aa[k], w.x);
            ffma2(h2b, aa[k], w.y);
        }

        float4 v1 = *(const float4*)(sv1 + j);
        float4 v2 = *(const float4*)(sv2 + j);
        float f0, f1, f2, f3;
        unpack2(f0, f1, h1a); unpack2(f2, f3, h1b);
        acc1 += fmaxf(f0, 0.0f) * v1.x + fmaxf(f1, 0.0f) * v1.y
              + fmaxf(f2, 0.0f) * v1.z + fmaxf(f3, 0.0f) * v1.w;
        unpack2(f0, f1, h2a); unpack2(f2, f3, h2b);
        acc2 += fmaxf(f0, 0.0f) * v2.x + fmaxf(f1, 0.0f) * v2.y
              + fmaxf(f2, 0.0f) * v2.z + fmaxf(f3, 0.0f) * v2.w;
    }

    float ga = 1.0f / (1.0f + expf(-acc1));
    float gb = 1.0f / (1.0f + expf(-acc2));
    g1[e] = ga;
    g2[e] = gb;
    int c = cols[e];
    atomicAdd(deg1 + c, ga);
    atomicAdd(deg2 + c, gb);
    atomicAdd(cnt + c, 1);
}

// ---------------------------------------------------------------------------
__global__ void rsqrt_kernel(float* d1, float* d2, int n) {
    int i = blockIdx.x * blockDim.x + threadIdx.x;
    if (i < n) {
        d1[i] = rsqrtf(d1[i]);
        d2[i] = rsqrtf(d2[i]);
    }
}

// ---------------------------------------------------------------------------
// Prefix sum over counts (3 kernels).
__global__ void scan_block_sums(const int* __restrict__ cnt, int* __restrict__ bsums, int n) {
    __shared__ int wsum[32];
    int i = blockIdx.x * 1024 + threadIdx.x;
    int v = (i < n) ? cnt[i] : 0;
    #pragma unroll
    for (int o = 16; o; o >>= 1) v += __shfl_down_sync(0xffffffffu, v, o);
    if ((threadIdx.x & 31) == 0) wsum[threadIdx.x >> 5] = v;
    __syncthreads();
    if (threadIdx.x < 32) {
        int s = wsum[threadIdx.x];
        #pragma unroll
        for (int o = 16; o; o >>= 1) s += __shfl_down_sync(0xffffffffu, s, o);
        if (threadIdx.x == 0) bsums[blockIdx.x] = s;
    }
}

__global__ void scan_bsums_excl(int* bsums, int nb) {
    if (threadIdx.x == 0 && blockIdx.x == 0) {
        int acc = 0;
        for (int i = 0; i < nb; i++) { int t = bsums[i]; bsums[i] = acc; acc += t; }
    }
}

__global__ void scan_final(const int* __restrict__ cnt, const int* __restrict__ bsums,
                           int* __restrict__ base, int n) {
    __shared__ int wsum[32];
    int i = blockIdx.x * 1024 + threadIdx.x;
    int v = (i < n) ? cnt[i] : 0;
    int lane = threadIdx.x & 31, w = threadIdx.x >> 5;
    int incl = v;
    #pragma unroll
    for (int o = 1; o < 32; o <<= 1) {
        int t = __shfl_up_sync(0xffffffffu, incl, o);
        if (lane >= o) incl += t;
    }
    if (lane == 31) wsum[w] = incl;
    __syncthreads();
    if (w == 0) {
        int s = wsum[lane];
        #pragma unroll
        for (int o = 1; o < 32; o <<= 1) {
            int t = __shfl_up_sync(0xffffffffu, s, o);
            if (lane >= o) s += t;
        }
        __syncwarp();
        wsum[lane] = s;
    }
    __syncthreads();
    int prev = (w == 0) ? 0 : wsum[w - 1];
    if (i < n) base[i] = incl - v + prev + bsums[blockIdx.x];
}

// ---------------------------------------------------------------------------
// CSR placement: one packed 16B record per edge slot:
//   {src_row (int bits), g*d1[r]*d1[c], g*d2[r]*d2[c], 0}
__global__ void place_kernel(const int* __restrict__ rows, const int* __restrict__ cols,
                             const float* __restrict__ g1, const float* __restrict__ g2,
                             const float* __restrict__ d1, const float* __restrict__ d2,
                             const int* __restrict__ base, int* __restrict__ cur,
                             float4* __restrict__ edges, int E)
{
    int e = blockIdx.x * blockDim.x + threadIdx.x;
    if (e >= E) return;
    int r = __ldg(rows + e);
    int c = __ldg(cols + e);
    int slot = __ldg(base + c) + atomicAdd(cur + c, 1);
    float4 rec;
    rec.x = __int_as_float(r);
    rec.y = __ldg(g1 + e) * __ldg(d1 + r) * __ldg(d1 + c);
    rec.z = __ldg(g2 + e) * __ldg(d2 + r) * __ldg(d2 + c);
    rec.w = 0.0f;
    edges[slot] = rec;
}

// ---------------------------------------------------------------------------
// Dense GEMM (f32x2): out[r][:] = act(X[r][:]) @ W, warp handles 4 rows.
// x staged into shared pre-packed as broadcast pairs {v,v}; W rows read as
// ulonglong2 (LDG.128, bits = 2 consecutive fp32 pairs).
__global__ void __launch_bounds__(256) gemm128_kernel(
    const float* __restrict__ X,
    const float* __restrict__ W,
    float* __restrict__ out, int n, int relu_in)
{
    __shared__ __align__(16) u64 xs[32 * 128];  // 32 KB: 32 rows, packed bcast pairs
    int warp = threadIdx.x >> 5;
    int lane = threadIdx.x & 31;

    for (int base = blockIdx.x * 32; base < n; base += gridDim.x * 32) {
        int r0 = base + warp * 4;
        #pragma unroll
        for (int i = 0; i < 4; i++) {
            int r = r0 + i;
            float4 v = make_float4(0.f, 0.f, 0.f, 0.f);
            if (r < n) v = ((const float4*)(X + (size_t)r * 128))[lane];
            if (relu_in) {
                v.x = fmaxf(v.x, 0.f); v.y = fmaxf(v.y, 0.f);
                v.z = fmaxf(v.z, 0.f); v.w = fmaxf(v.w, 0.f);
            }
            u64* dst = xs + (warp * 4 + i) * 128 + lane * 4;
            dst[0] = bcast2(v.x); dst[1] = bcast2(v.y);
            dst[2] = bcast2(v.z); dst[3] = bcast2(v.w);
        }
        __syncwarp();

        u64 a0x = 0, a0y = 0, a1x = 0, a1y = 0;
        u64 a2x = 0, a2y = 0, a3x = 0, a3y = 0;
        const u64* x0 = xs + warp * 4 * 128;

        #pragma unroll 8
        for (int k = 0; k < 128; k++) {
            ulonglong2 w = __ldg((const ulonglong2*)(W + k * 128) + lane);
            u64 xa = x0[k], xb = x0[128 + k], xc = x0[256 + k], xd = x0[384 + k];
            ffma2(a0x, xa, w.x); ffma2(a0y, xa, w.y);
            ffma2(a1x, xb, w.x); ffma2(a1y, xb, w.y);
            ffma2(a2x, xc, w.x); ffma2(a2y, xc, w.y);
            ffma2(a3x, xd, w.x); ffma2(a3y, xd, w.y);
        }

        if (r0 + 0 < n) ((ulonglong2*)(out + (size_t)(r0 + 0) * 128))[lane] = make_ulonglong2(a0x, a0y);
        if (r0 + 1 < n) ((ulonglong2*)(out + (size_t)(r0 + 1) * 128))[lane] = make_ulonglong2(a1x, a1y);
        if (r0 + 2 < n) ((ulonglong2*)(out + (size_t)(r0 + 2) * 128))[lane] = make_ulonglong2(a2x, a2y);
        if (r0 + 3 < n) ((ulonglong2*)(out + (size_t)(r0 + 3) * 128))[lane] = make_ulonglong2(a3x, a3y);
        __syncwarp();
    }
}

// ---------------------------------------------------------------------------
// Gather-aggregate: one warp per node; self-loop fused into accumulator init.
// 4-way unrolled for MLP against ~250cyc L2 latency.
__global__ void __launch_bounds__(256)
gather_kernel(const float* __restrict__ h,
              const float* __restrict__ dinv,
              const int* __restrict__ base,
              const int* __restrict__ cnt,
              const float4* __restrict__ edges,
              float* __restrict__ out, int n, int sel)
{
    int node = blockIdx.x * (blockDim.x >> 5) + (threadIdx.x >> 5);
    if (node >= n) return;
    int lane = threadIdx.x & 31;

    float di = __ldg(dinv + node);
    float w0 = di * di;
    float4 acc = __ldg((const float4*)(h + (size_t)node * 128) + lane);
    acc.x *= w0; acc.y *= w0; acc.z *= w0; acc.w *= w0;

    int s = __ldg(base + node);
    int end = s + __ldg(cnt + node);

    for (; s + 4 <= end; s += 4) {
        float4 e0 = __ldg(edges + s);
        float4 e1 = __ldg(edges + s + 1);
        float4 e2 = __ldg(edges + s + 2);
        float4 e3 = __ldg(edges + s + 3);
        int r0 = __float_as_int(e0.x);
        int r1 = __float_as_int(e1.x);
        int r2 = __float_as_int(e2.x);
        int r3 = __float_as_int(e3.x);
        float w0_ = sel ? e0.z : e0.y;
        float w1_ = sel ? e1.z : e1.y;
        float w2_ = sel ? e2.z : e2.y;
        float w3_ = sel ? e3.z : e3.y;
        float4 v0 = __ldg((const float4*)(h + (size_t)r0 * 128) + lane);
        float4 v1 = __ldg((const float4*)(h + (size_t)r1 * 128) + lane);
        float4 v2 = __ldg((const float4*)(h + (size_t)r2 * 128) + lane);
        float4 v3 = __ldg((const float4*)(h + (size_t)r3 * 128) + lane);
        acc.x = fmaf(w0_, v0.x, acc.x); acc.y = fmaf(w0_, v0.y, acc.y);
        acc.z = fmaf(w0_, v0.z, acc.z); acc.w = fmaf(w0_, v0.w, acc.w);
        acc.x = fmaf(w1_, v1.x, acc.x); acc.y = fmaf(w1_, v1.y, acc.y);
        acc.z = fmaf(w1_, v1.z, acc.z); acc.w = fmaf(w1_, v1.w, acc.w);
        acc.x = fmaf(w2_, v2.x, acc.x); acc.y = fmaf(w2_, v2.y, acc.y);
        acc.z = fmaf(w2_, v2.z, acc.z); acc.w = fmaf(w2_, v2.w, acc.w);
        acc.x = fmaf(w3_, v3.x, acc.x); acc.y = fmaf(w3_, v3.y, acc.y);
        acc.z = fmaf(w3_, v3.z, acc.z); acc.w = fmaf(w3_, v3.w, acc.w);
    }
    for (; s < end; s++) {
        float4 e0 = __ldg(edges + s);
        int r0 = __float_as_int(e0.x);
        float wa = sel ? e0.z : e0.y;
        float4 v0 = __ldg((const float4*)(h + (size_t)r0 * 128) + lane);
        acc.x = fmaf(wa, v0.x, acc.x); acc.y = fmaf(wa, v0.y, acc.y);
        acc.z = fmaf(wa, v0.z, acc.z); acc.w = fmaf(wa, v0.w, acc.w);
    }

    ((float4*)(out + (size_t)node * 128))[lane] = acc;
}

// ---------------------------------------------------------------------------
extern "C" void kernel_launch(void* const* d_in, const int* in_sizes, int n_in,
                              void* d_out, int out_size)
{
    const float* x    = (const float*)d_in[0];
    const int*   ei   = (const int*)  d_in[1];
    const float* ea   = (const float*)d_in[2];
    const float* W1   = (const float*)d_in[3];
    const float* m1w1 = (const float*)d_in[4];
    const float* m1b1 = (const float*)d_in[5];
    const float* m1w2 = (const float*)d_in[6];
    const float* m1b2 = (const float*)d_in[7];
    const float* W2   = (const float*)d_in[8];
    const float* m2w1 = (const float*)d_in[9];
    const float* m2b1 = (const float*)d_in[10];
    const float* m2w2 = (const float*)d_in[11];
    const float* m2b2 = (const float*)d_in[12];
    float* out = (float*)d_out;

    int n = in_sizes[0] / 128;   // 100000
    int E = in_sizes[1] / 2;     // 1600000
    const int* rows = ei;
    const int* cols = ei + E;
    int nblk = (n + 1023) / 1024;

    float *ph, *pagg, *pg1, *pg2, *pd1, *pd2;
    float4* pedges;
    int *pcnt, *pcur, *pbase, *pbsums;
    cudaGetSymbolAddress((void**)&ph,     g_h);
    cudaGetSymbolAddress((void**)&pagg,   g_agg);
    cudaGetSymbolAddress((void**)&pg1,    g_g1);
    cudaGetSymbolAddress((void**)&pg2,    g_g2);
    cudaGetSymbolAddress((void**)&pd1,    g_d1);
    cudaGetSymbolAddress((void**)&pd2,    g_d2);
    cudaGetSymbolAddress((void**)&pcnt,   g_cnt);
    cudaGetSymbolAddress((void**)&pcur,   g_cur);
    cudaGetSymbolAddress((void**)&pbase,  g_base);
    cudaGetSymbolAddress((void**)&pbsums, g_bsums);
    cudaGetSymbolAddress((void**)&pedges, g_edges);

    // Phase A: gates + degrees + counts
    init_kernel<<<(n + 255) / 256, 256>>>(pd1, pd2, pcnt, pcur, n);
    gate_kernel<<<(E + 255) / 256, 256>>>(ea,
                                          m1w1, m1b1, m1w2, m1b2,
                                          m2w1, m2b1, m2w2, m2b2,
                                          cols, pg1, pg2, pd1, pd2, pcnt, E);
    rsqrt_kernel<<<(n + 255) / 256, 256>>>(pd1, pd2, n);

    // Phase B: CSR build
    scan_block_sums<<<nblk, 1024>>>(pcnt, pbsums, n);
    scan_bsums_excl<<<1, 32>>>(pbsums, nblk);
    scan_final<<<nblk, 1024>>>(pcnt, pbsums, pbase, n);
    place_kernel<<<(E + 255) / 256, 256>>>(rows, cols, pg1, pg2, pd1, pd2,
                                           pbase, pcur, pedges, E);

    // Phase C: layer 1 (GEMM, then gather with fused self-loop)
    gemm128_kernel<<<592, 256>>>(x, W1, ph, n, 0);
    gather_kernel<<<(n + 7) / 8, 256>>>(ph, pd1, pbase, pcnt, pedges, pagg, n, 0);

    // Phase D: layer 2 (relu fused into GEMM input)
    gemm128_kernel<<<592, 256>>>(pagg, W2, ph, n, 1);
    gather_kernel<<<(n + 7) / 8, 256>>>(ph, pd2, pbase, pcnt, pedges, out, n, 1);
}

// round 5
// speedup vs baseline: 1.0082x; 1.0082x over previous
#include <cuda_runtime.h>
#include <math.h>

#define MAXN 100000
#define MAXE 1600000
#define NBLK 98          // ceil(MAXN/1024) for scans

typedef unsigned long long u64;

// ---- packed f32x2 helpers (sm_100+: one issue slot = 2 fp32 FMAs) ----------
__device__ __forceinline__ u64 bcast2(float v) {
    u64 r; asm("mov.b64 %0, {%1, %1};" : "=l"(r) : "f"(v)); return r;
}
__device__ __forceinline__ void ffma2(u64& d, u64 a, u64 b) {
    asm("fma.rn.f32x2 %0, %1, %2, %0;" : "+l"(d) : "l"(a), "l"(b));
}
__device__ __forceinline__ void unpack2(float& lo, float& hi, u64 v) {
    asm("mov.b64 {%0, %1}, %2;" : "=f"(lo), "=f"(hi) : "l"(v));
}

// Scratch (__device__ globals; no allocation allowed)
__device__ float  g_h[(size_t)MAXN * 128];    // h = x @ W (per layer)
__device__ float  g_agg[(size_t)MAXN * 128];  // aggregated layer-1 output
__device__ float  g_g1[MAXE];                 // edge gates layer 1
__device__ float  g_g2[MAXE];                 // edge gates layer 2
__device__ float  g_d1[MAXN];                 // deg -> rsqrt(deg) layer 1
__device__ float  g_d2[MAXN];                 // deg -> rsqrt(deg) layer 2
__device__ int    g_cnt[MAXN];                // in-degree counts
__device__ int    g_cur[MAXN];                // placement cursors
__device__ int    g_base[MAXN];               // CSR base offsets
__device__ int    g_bsums[NBLK + 1];          // scan block sums
__device__ float4 g_edges[MAXE];              // CSR slot: {row(bits), w1, w2, 0}

// ---------------------------------------------------------------------------
__global__ void init_kernel(float* d1, float* d2, int* cnt, int* cur, int n) {
    int i = blockIdx.x * blockDim.x + threadIdx.x;
    if (i < n) { d1[i] = 1.0f; d2[i] = 1.0f; cnt[i] = 0; cur[i] = 0; }
}

// ---------------------------------------------------------------------------
// Edge gate MLPs for BOTH layers in one pass (f32x2 packed math);
// also weighted in-degree and count histogram (for CSR).
__global__ void __launch_bounds__(256) gate_kernel(
    const float* __restrict__ ea,
    const float* __restrict__ w1a, const float* __restrict__ b1a,
    const float* __restrict__ w2a, const float* __restrict__ b2a,
    const float* __restrict__ w1b, const float* __restrict__ b1b,
    const float* __restrict__ w2b, const float* __restrict__ b2b,
    const int* __restrict__ cols,
    float* __restrict__ g1, float* __restrict__ g2,
    float* __restrict__ deg1, float* __restrict__ deg2,
    int* __restrict__ cnt, int E)
{
    __shared__ __align__(16) float s1[16 * 128];
    __shared__ __align__(16) float s2[16 * 128];
    __shared__ __align__(16) float sb1[128], sb2[128], sv1[128], sv2[128];

    int tid = threadIdx.x;
    for (int i = tid; i < 2048; i += blockDim.x) { s1[i] = w1a[i]; s2[i] = w1b[i]; }
    if (tid < 128) {
        sb1[tid] = b1a[tid]; sb2[tid] = b1b[tid];
        sv1[tid] = w2a[tid]; sv2[tid] = w2b[tid];
    }
    __syncthreads();

    int e = blockIdx.x * blockDim.x + tid;
    if (e >= E) return;

    // load 16 edge attrs, pack each as a broadcast f32x2 pair
    u64 aa[16];
    {
        const float4* p = (const float4*)(ea + (size_t)e * 16);
        float4 q0 = p[0], q1 = p[1], q2 = p[2], q3 = p[3];
        aa[0]  = bcast2(q0.x); aa[1]  = bcast2(q0.y); aa[2]  = bcast2(q0.z); aa[3]  = bcast2(q0.w);
        aa[4]  = bcast2(q1.x); aa[5]  = bcast2(q1.y); aa[6]  = bcast2(q1.z); aa[7]  = bcast2(q1.w);
        aa[8]  = bcast2(q2.x); aa[9]  = bcast2(q2.y); aa[10] = bcast2(q2.z); aa[11] = bcast2(q2.w);
        aa[12] = bcast2(q3.x); aa[13] = bcast2(q3.y); aa[14] = bcast2(q3.z); aa[15] = bcast2(q3.w);
    }

    float acc1 = b2a[0];
    float acc2 = b2b[0];

    #pragma unroll 1
    for (int j = 0; j < 128; j += 4) {
        // hidden accumulators for 4 cols = 2 packed pairs per layer, init = bias
        ulonglong2 hb1 = *(const ulonglong2*)(sb1 + j);
        ulonglong2 hb2 = *(const ulonglong2*)(sb2 + j);
        u64 h1a = hb1.x, h1b = hb1.y;
        u64 h2a = hb2.x, h2b = hb2.y;

        #pragma unroll
        for (int k = 0; k < 16; k++) {
            ulonglong2 w = *(const ulonglong2*)(s1 + k * 128 + j);   // LDS.128
            ffma2(h1a, aa[k], w.x);
            ffma2(h1b, aa[k], w.y);
        }
        #pragma unroll
        for (int k = 0; k < 16; k++) {
            ulonglong2 w = *(const ulonglong2*)(s2 + k * 128 + j);
            ffma2(h2a, aa[k], w.x);
            ffma2(h2b, aa[k], w.y);
        }

        float4 v1 = *(const float4*)(sv1 + j);
        float4 v2 = *(const float4*)(sv2 + j);
        float f0, f1, f2, f3;
        unpack2(f0, f1, h1a); unpack2(f2, f3, h1b);
        acc1 += fmaxf(f0, 0.0f) * v1.x + fmaxf(f1, 0.0f) * v1.y
              + fmaxf(f2, 0.0f) * v1.z + fmaxf(f3, 0.0f) * v1.w;
        unpack2(f0, f1, h2a); unpack2(f2, f3, h2b);
        acc2 += fmaxf(f0, 0.0f) * v2.x + fmaxf(f1, 0.0f) * v2.y
              + fmaxf(f2, 0.0f) * v2.z + fmaxf(f3, 0.0f) * v2.w;
    }

    float ga = 1.0f / (1.0f + expf(-acc1));
    float gb = 1.0f / (1.0f + expf(-acc2));
    g1[e] = ga;
    g2[e] = gb;
    int c = cols[e];
    atomicAdd(deg1 + c, ga);
    atomicAdd(deg2 + c, gb);
    atomicAdd(cnt + c, 1);
}

// ---------------------------------------------------------------------------
__global__ void rsqrt_kernel(float* d1, float* d2, int n) {
    int i = blockIdx.x * blockDim.x + threadIdx.x;
    if (i < n) {
        d1[i] = rsqrtf(d1[i]);
        d2[i] = rsqrtf(d2[i]);
    }
}

// ---------------------------------------------------------------------------
// Prefix sum over counts (3 kernels).
__global__ void scan_block_sums(const int* __restrict__ cnt, int* __restrict__ bsums, int n) {
    __shared__ int wsum[32];
    int i = blockIdx.x * 1024 + threadIdx.x;
    int v = (i < n) ? cnt[i] : 0;
    #pragma unroll
    for (int o = 16; o; o >>= 1) v += __shfl_down_sync(0xffffffffu, v, o);
    if ((threadIdx.x & 31) == 0) wsum[threadIdx.x >> 5] = v;
    __syncthreads();
    if (threadIdx.x < 32) {
        int s = wsum[threadIdx.x];
        #pragma unroll
        for (int o = 16; o; o >>= 1) s += __shfl_down_sync(0xffffffffu, s, o);
        if (threadIdx.x == 0) bsums[blockIdx.x] = s;
    }
}

__global__ void scan_bsums_excl(int* bsums, int nb) {
    if (threadIdx.x == 0 && blockIdx.x == 0) {
        int acc = 0;
        for (int i = 0; i < nb; i++) { int t = bsums[i]; bsums[i] = acc; acc += t; }
    }
}

__global__ void scan_final(const int* __restrict__ cnt, const int* __restrict__ bsums,
                           int* __restrict__ base, int n) {
    __shared__ int wsum[32];
    int i = blockIdx.x * 1024 + threadIdx.x;
    int v = (i < n) ? cnt[i] : 0;
    int lane = threadIdx.x & 31, w = threadIdx.x >> 5;
    int incl = v;
    #pragma unroll
    for (int o = 1; o < 32; o <<= 1) {
        int t = __shfl_up_sync(0xffffffffu, incl, o);
        if (lane >= o) incl += t;
    }
    if (lane == 31) wsum[w] = incl;
    __syncthreads();
    if (w == 0) {
        int s = wsum[lane];
        #pragma unroll
        for (int o = 1; o < 32; o <<= 1) {
            int t = __shfl_up_sync(0xffffffffu, s, o);
            if (lane >= o) s += t;
        }
        __syncwarp();
        wsum[lane] = s;
    }
    __syncthreads();
    int prev = (w == 0) ? 0 : wsum[w - 1];
    if (i < n) base[i] = incl - v + prev + bsums[blockIdx.x];
}

// ---------------------------------------------------------------------------
// CSR placement: one packed 16B record per edge slot:
//   {src_row (int bits), g*d1[r]*d1[c], g*d2[r]*d2[c], 0}
__global__ void place_kernel(const int* __restrict__ rows, const int* __restrict__ cols,
                             const float* __restrict__ g1, const float* __restrict__ g2,
                             const float* __restrict__ d1, const float* __restrict__ d2,
                             const int* __restrict__ base, int* __restrict__ cur,
                             float4* __restrict__ edges, int E)
{
    int e = blockIdx.x * blockDim.x + threadIdx.x;
    if (e >= E) return;
    int r = __ldg(rows + e);
    int c = __ldg(cols + e);
    int slot = __ldg(base + c) + atomicAdd(cur + c, 1);
    float4 rec;
    rec.x = __int_as_float(r);
    rec.y = __ldg(g1 + e) * __ldg(d1 + r) * __ldg(d1 + c);
    rec.z = __ldg(g2 + e) * __ldg(d2 + r) * __ldg(d2 + c);
    rec.w = 0.0f;
    edges[slot] = rec;
}

// ---------------------------------------------------------------------------
// Dense GEMM (f32x2): out[r][:] = act(X[r][:]) @ W, warp handles 4 rows.
// x staged into shared pre-packed as broadcast pairs {v,v}; W rows read as
// ulonglong2 (LDG.128, bits = 2 consecutive fp32 pairs).
__global__ void __launch_bounds__(256) gemm128_kernel(
    const float* __restrict__ X,
    const float* __restrict__ W,
    float* __restrict__ out, int n, int relu_in)
{
    __shared__ __align__(16) u64 xs[32 * 128];  // 32 KB: 32 rows, packed bcast pairs
    int warp = threadIdx.x >> 5;
    int lane = threadIdx.x & 31;

    for (int base = blockIdx.x * 32; base < n; base += gridDim.x * 32) {
        int r0 = base + warp * 4;
        #pragma unroll
        for (int i = 0; i < 4; i++) {
            int r = r0 + i;
            float4 v = make_float4(0.f, 0.f, 0.f, 0.f);
            if (r < n) v = ((const float4*)(X + (size_t)r * 128))[lane];
            if (relu_in) {
                v.x = fmaxf(v.x, 0.f); v.y = fmaxf(v.y, 0.f);
                v.z = fmaxf(v.z, 0.f); v.w = fmaxf(v.w, 0.f);
            }
            u64* dst = xs + (warp * 4 + i) * 128 + lane * 4;
            dst[0] = bcast2(v.x); dst[1] = bcast2(v.y);
            dst[2] = bcast2(v.z); dst[3] = bcast2(v.w);
        }
        __syncwarp();

        u64 a0x = 0, a0y = 0, a1x = 0, a1y = 0;
        u64 a2x = 0, a2y = 0, a3x = 0, a3y = 0;
        const u64* x0 = xs + warp * 4 * 128;

        #pragma unroll 8
        for (int k = 0; k < 128; k++) {
            ulonglong2 w = __ldg((const ulonglong2*)(W + k * 128) + lane);
            u64 xa = x0[k], xb = x0[128 + k], xc = x0[256 + k], xd = x0[384 + k];
            ffma2(a0x, xa, w.x); ffma2(a0y, xa, w.y);
            ffma2(a1x, xb, w.x); ffma2(a1y, xb, w.y);
            ffma2(a2x, xc, w.x); ffma2(a2y, xc, w.y);
            ffma2(a3x, xd, w.x); ffma2(a3y, xd, w.y);
        }

        if (r0 + 0 < n) ((ulonglong2*)(out + (size_t)(r0 + 0) * 128))[lane] = make_ulonglong2(a0x, a0y);
        if (r0 + 1 < n) ((ulonglong2*)(out + (size_t)(r0 + 1) * 128))[lane] = make_ulonglong2(a1x, a1y);
        if (r0 + 2 < n) ((ulonglong2*)(out + (size_t)(r0 + 2) * 128))[lane] = make_ulonglong2(a2x, a2y);
        if (r0 + 3 < n) ((ulonglong2*)(out + (size_t)(r0 + 3) * 128))[lane] = make_ulonglong2(a3x, a3y);
        __syncwarp();
    }
}

// ---------------------------------------------------------------------------
// Gather-aggregate: one warp per node; self-loop fused into accumulator init.
// 4-way unrolled for MLP against ~250cyc L2 latency.
__global__ void __launch_bounds__(256)
gather_kernel(const float* __restrict__ h,
              const float* __restrict__ dinv,
              const int* __restrict__ base,
              const int* __restrict__ cnt,
              const float4* __restrict__ edges,
              float* __restrict__ out, int n, int sel)
{
    int node = blockIdx.x * (blockDim.x >> 5) + (threadIdx.x >> 5);
    if (node >= n) return;
    int lane = threadIdx.x & 31;

    float di = __ldg(dinv + node);
    float w0 = di * di;
    float4 acc = __ldg((const float4*)(h + (size_t)node * 128) + lane);
    acc.x *= w0; acc.y *= w0; acc.z *= w0; acc.w *= w0;

    int s = __ldg(base + node);
    int end = s + __ldg(cnt + node);

    for (; s + 4 <= end; s += 4) {
        float4 e0 = __ldg(edges + s);
        float4 e1 = __ldg(edges + s + 1);
        float4 e2 = __ldg(edges + s + 2);
        float4 e3 = __ldg(edges + s + 3);
        int r0 = __float_as_int(e0.x);
        int r1 = __float_as_int(e1.x);
        int r2 = __float_as_int(e2.x);
        int r3 = __float_as_int(e3.x);
        float w0_ = sel ? e0.z : e0.y;
        float w1_ = sel ? e1.z : e1.y;
        float w2_ = sel ? e2.z : e2.y;
        float w3_ = sel ? e3.z : e3.y;
        float4 v0 = __ldg((const float4*)(h + (size_t)r0 * 128) + lane);
        float4 v1 = __ldg((const float4*)(h + (size_t)r1 * 128) + lane);
        float4 v2 = __ldg((const float4*)(h + (size_t)r2 * 128) + lane);
        float4 v3 = __ldg((const float4*)(h + (size_t)r3 * 128) + lane);
        acc.x = fmaf(w0_, v0.x, acc.x); acc.y = fmaf(w0_, v0.y, acc.y);
        acc.z = fmaf(w0_, v0.z, acc.z); acc.w = fmaf(w0_, v0.w, acc.w);
        acc.x = fmaf(w1_, v1.x, acc.x); acc.y = fmaf(w1_, v1.y, acc.y);
        acc.z = fmaf(w1_, v1.z, acc.z); acc.w = fmaf(w1_, v1.w, acc.w);
        acc.x = fmaf(w2_, v2.x, acc.x); acc.y = fmaf(w2_, v2.y, acc.y);
        acc.z = fmaf(w2_, v2.z, acc.z); acc.w = fmaf(w2_, v2.w, acc.w);
        acc.x = fmaf(w3_, v3.x, acc.x); acc.y = fmaf(w3_, v3.y, acc.y);
        acc.z = fmaf(w3_, v3.z, acc.z); acc.w = fmaf(w3_, v3.w, acc.w);
    }
    for (; s < end; s++) {
        float4 e0 = __ldg(edges + s);
        int r0 = __float_as_int(e0.x);
        float wa = sel ? e0.z : e0.y;
        float4 v0 = __ldg((const float4*)(h + (size_t)r0 * 128) + lane);
        acc.x = fmaf(wa, v0.x, acc.x); acc.y = fmaf(wa, v0.y, acc.y);
        acc.z = fmaf(wa, v0.z, acc.z); acc.w = fmaf(wa, v0.w, acc.w);
    }

    ((float4*)(out + (size_t)node * 128))[lane] = acc;
}

// ---------------------------------------------------------------------------
extern "C" void kernel_launch(void* const* d_in, const int* in_sizes, int n_in,
                              void* d_out, int out_size)
{
    const float* x    = (const float*)d_in[0];
    const int*   ei   = (const int*)  d_in[1];
    const float* ea   = (const float*)d_in[2];
    const float* W1   = (const float*)d_in[3];
    const float* m1w1 = (const float*)d_in[4];
    const float* m1b1 = (const float*)d_in[5];
    const float* m1w2 = (const float*)d_in[6];
    const float* m1b2 = (const float*)d_in[7];
    const float* W2   = (const float*)d_in[8];
    const float* m2w1 = (const float*)d_in[9];
    const float* m2b1 = (const float*)d_in[10];
    const float* m2w2 = (const float*)d_in[11];
    const float* m2b2 = (const float*)d_in[12];
    float* out = (float*)d_out;

    int n = in_sizes[0] / 128;   // 100000
    int E = in_sizes[1] / 2;     // 1600000
    const int* rows = ei;
    const int* cols = ei + E;
    int nblk = (n + 1023) / 1024;

    float *ph, *pagg, *pg1, *pg2, *pd1, *pd2;
    float4* pedges;
    int *pcnt, *pcur, *pbase, *pbsums;
    cudaGetSymbolAddress((void**)&ph,     g_h);
    cudaGetSymbolAddress((void**)&pagg,   g_agg);
    cudaGetSymbolAddress((void**)&pg1,    g_g1);
    cudaGetSymbolAddress((void**)&pg2,    g_g2);
    cudaGetSymbolAddress((void**)&pd1,    g_d1);
    cudaGetSymbolAddress((void**)&pd2,    g_d2);
    cudaGetSymbolAddress((void**)&pcnt,   g_cnt);
    cudaGetSymbolAddress((void**)&pcur,   g_cur);
    cudaGetSymbolAddress((void**)&pbase,  g_base);
    cudaGetSymbolAddress((void**)&pbsums, g_bsums);
    cudaGetSymbolAddress((void**)&pedges, g_edges);

    // Phase A: gates + degrees + counts
    init_kernel<<<(n + 255) / 256, 256>>>(pd1, pd2, pcnt, pcur, n);
    gate_kernel<<<(E + 255) / 256, 256>>>(ea,
                                          m1w1, m1b1, m1w2, m1b2,
                                          m2w1, m2b1, m2w2, m2b2,
                                          cols, pg1, pg2, pd1, pd2, pcnt, E);
    rsqrt_kernel<<<(n + 255) / 256, 256>>>(pd1, pd2, n);

    // Phase B: CSR build
    scan_block_sums<<<nblk, 1024>>>(pcnt, pbsums, n);
    scan_bsums_excl<<<1, 32>>>(pbsums, nblk);
    scan_final<<<nblk, 1024>>>(pcnt, pbsums, pbase, n);
    place_kernel<<<(E + 255) / 256, 256>>>(rows, cols, pg1, pg2, pd1, pd2,
                                           pbase, pcur, pedges, E);

    // Phase C: layer 1 (GEMM, then gather with fused self-loop)
    gemm128_kernel<<<592, 256>>>(x, W1, ph, n, 0);
    gather_kernel<<<(n + 7) / 8, 256>>>(ph, pd1, pbase, pcnt, pedges, pagg, n, 0);

    // Phase D: layer 2 (relu fused into GEMM input)
    gemm128_kernel<<<592, 256>>>(pagg, W2, ph, n, 1);
    gather_kernel<<<(n + 7) / 8, 256>>>(ph, pd2, pbase, pcnt, pedges, out, n, 1);
}

// round 7
// speedup vs baseline: 1.2627x; 1.2525x over previous
#include <cuda_runtime.h>
#include <math.h>
#include <cstdint>

#define MAXN 100000
#define MAXE 1600000
#define NBLK 98
typedef unsigned long long u64;

__device__ __forceinline__ u64 bcast2(float v){u64 r;asm("mov.b64 %0,{%1,%1};":"=l"(r):"f"(v));return r;}
__device__ __forceinline__ void ffma2(u64&d,u64 a,u64 b){asm("fma.rn.f32x2 %0,%1,%2,%0;":"+l"(d):"l"(a),"l"(b));}
__device__ __forceinline__ float tf32_hi(float x){return __uint_as_float(__float_as_uint(x)&0xffffe000u);}

// m16n8k8 tf32 mma (sm_80+ PTX, no 'a' feature needed)
__device__ __forceinline__ void mma8(float* c,const uint32_t* a,uint32_t b0,uint32_t b1){
    asm volatile("mma.sync.aligned.m16n8k8.row.col.f32.tf32.tf32.f32 "
                 "{%0,%1,%2,%3},{%4,%5,%6,%7},{%8,%9},{%0,%1,%2,%3};"
        :"+f"(c[0]),"+f"(c[1]),"+f"(c[2]),"+f"(c[3])
        :"r"(a[0]),"r"(a[1]),"r"(a[2]),"r"(a[3]),"r"(b0),"r"(b1));
}

__device__ float  g_h[(size_t)MAXN*128];
__device__ float  g_agg[(size_t)MAXN*128];
__device__ float  g_g1[MAXE];
__device__ float  g_g2[MAXE];
__device__ float  g_d1[MAXN];
__device__ float  g_d2[MAXN];
__device__ int    g_cnt[MAXN];
__device__ int    g_cur[MAXN];
__device__ int    g_base[MAXN];
__device__ int    g_bsums[NBLK+1];
__device__ float4 g_edges[MAXE];

__global__ void init_kernel(float*d1,float*d2,int*cnt,int*cur,int n){
    int i=blockIdx.x*blockDim.x+threadIdx.x;
    if(i<n){d1[i]=1.0f;d2[i]=1.0f;cnt[i]=0;cur[i]=0;}
}

// ---------------------------------------------------------------------------
// Tensor-core gate via mma.sync tf32, split-fp32 K=48, bias in C-init.
// Warp task = 64 edges (4 x m16 tiles). B (weights) staged in shared,
// stride 136 floats (bank = 8k+n -> conflict-free for the b0/b1 pattern).
// Smem: Bs[2][48*136] | bias[2][128] | w2[2][128]  = 54272 B dynamic.
__global__ void __launch_bounds__(256) gate_mma_kernel(
    const float* __restrict__ ea,
    const float* __restrict__ m1w1,const float* __restrict__ m1b1,
    const float* __restrict__ m1w2,const float* __restrict__ m1b2,
    const float* __restrict__ m2w1,const float* __restrict__ m2b1,
    const float* __restrict__ m2w2,const float* __restrict__ m2b2,
    const int* __restrict__ cols,
    float* __restrict__ g1,float* __restrict__ g2,
    float* __restrict__ deg1,float* __restrict__ deg2,int* __restrict__ cnt,int E)
{
    extern __shared__ float ds[];
    float* biasp=ds+2*48*136;     // 13056
    float* w2p  =biasp+256;
    int tid=threadIdx.x;

    for(int idx=tid;idx<2*48*128;idx+=256){
        int layer=idx/6144,rem=idx%6144,k=rem>>7,n=rem&127;
        const float* W=layer?m2w1:m1w1;
        float v;
        if(k<16)      v=tf32_hi(__ldg(W+k*128+n));
        else if(k<32) v=tf32_hi(__ldg(W+(k-16)*128+n));
        else          {float w=__ldg(W+(k-32)*128+n);v=w-tf32_hi(w);}
        ds[layer*6528+k*136+n]=v;
    }
    if(tid<256){
        biasp[tid]=(tid<128)?__ldg(m1b1+tid):__ldg(m2b1+tid-128);
        w2p[tid]  =(tid<128)?__ldg(m1w2+tid):__ldg(m2w2+tid-128);
    }
    __syncthreads();

    int lane=tid&31,g=lane>>2,t=lane&3;
    int w=blockIdx.x*(blockDim.x>>5)+(tid>>5);
    int nwarps=gridDim.x*(blockDim.x>>5);
    int ntask=(E+63)>>6;
    float b2v[2]={__ldg(m1b2),__ldg(m2b2)};

    for(int task=w;task<ntask;task+=nwarps){
        int e0=task*64;
        // Build A fragments (hi/lo) for 4 m-tiles, register-resident.
        // frag layout (m16n8k8 row-major A): a0=(g,c), a1=(g+8,c), a2=(g,c+4), a3=(g+8,c+4)
        uint32_t Ahi[4][8],Alo[4][8];
        #pragma unroll
        for(int mt=0;mt<4;mt++){
            int r1=e0+mt*16+g,r2=r1+8;
            #pragma unroll
            for(int j=0;j<4;j++){
                int ac=(j&1)*4+(j>>1)*8+t;           // t, t+4, 8+t, 12+t
                int fi=(j>>1)*4+(j&1)*2;             // frag slot
                float v1=(r1<E)?__ldg(ea+(size_t)r1*16+ac):0.f;
                float v2=(r2<E)?__ldg(ea+(size_t)r2*16+ac):0.f;
                uint32_t h1=__float_as_uint(v1)&0xffffe000u;
                uint32_t h2=__float_as_uint(v2)&0xffffe000u;
                Ahi[mt][fi]=h1;  Ahi[mt][fi+1]=h2;
                Alo[mt][fi]=__float_as_uint(v1-__uint_as_float(h1));
                Alo[mt][fi+1]=__float_as_uint(v2-__uint_as_float(h2));
            }
        }
        #pragma unroll
        for(int layer=0;layer<2;layer++){
            const float* Bl=ds+layer*6528;
            const float* biasl=biasp+layer*128;
            const float* w2l=w2p+layer*128;
            float p0[4]={0,0,0,0},p1[4]={0,0,0,0};
            #pragma unroll 1
            for(int nt=0;nt<16;nt++){
                int n0=nt*8;
                float bA=biasl[n0+2*t],bB=biasl[n0+2*t+1];
                float c[4][4];
                #pragma unroll
                for(int mt=0;mt<4;mt++){c[mt][0]=bA;c[mt][1]=bB;c[mt][2]=bA;c[mt][3]=bB;}
                // B frag (col-major): b0=(k0+t, n0+g), b1=(k0+t+4, n0+g)
                #define STEP(AARR,OFF,K0) do{                                   \
                    uint32_t b0=__float_as_uint(Bl[(K0+t)*136+n0+g]);           \
                    uint32_t b1v=__float_as_uint(Bl[(K0+t+4)*136+n0+g]);        \
                    _Pragma("unroll")                                           \
                    for(int mt=0;mt<4;mt++) mma8(c[mt],&AARR[mt][OFF],b0,b1v);  \
                }while(0)
                STEP(Ahi,0,0);  STEP(Ahi,4,8);    // hi * W_hi
                STEP(Alo,0,16); STEP(Alo,4,24);   // lo * W_hi
                STEP(Ahi,0,32); STEP(Ahi,4,40);   // hi * W_lo
                #undef STEP
                float wA=w2l[n0+2*t],wB=w2l[n0+2*t+1];
                #pragma unroll
                for(int mt=0;mt<4;mt++){
                    p0[mt]+=fmaxf(c[mt][0],0.f)*wA+fmaxf(c[mt][1],0.f)*wB;
                    p1[mt]+=fmaxf(c[mt][2],0.f)*wA+fmaxf(c[mt][3],0.f)*wB;
                }
            }
            #pragma unroll
            for(int mt=0;mt<4;mt++){
                p0[mt]+=__shfl_xor_sync(0xffffffffu,p0[mt],1);
                p0[mt]+=__shfl_xor_sync(0xffffffffu,p0[mt],2);
                p1[mt]+=__shfl_xor_sync(0xffffffffu,p1[mt],1);
                p1[mt]+=__shfl_xor_sync(0xffffffffu,p1[mt],2);
            }
            if(t==0){
                float b2=b2v[layer];
                #pragma unroll
                for(int mt=0;mt<4;mt++){
                    int e=e0+mt*16+g;
                    if(e<E){
                        float gg=1.0f/(1.0f+expf(-(p0[mt]+b2)));
                        int c_=__ldg(cols+e);
                        if(layer==0){g1[e]=gg;atomicAdd(deg1+c_,gg);atomicAdd(cnt+c_,1);}
                        else        {g2[e]=gg;atomicAdd(deg2+c_,gg);}
                    }
                    int e2=e0+mt*16+g+8;
                    if(e2<E){
                        float gg=1.0f/(1.0f+expf(-(p1[mt]+b2)));
                        int c_=__ldg(cols+e2);
                        if(layer==0){g1[e2]=gg;atomicAdd(deg1+c_,gg);atomicAdd(cnt+c_,1);}
                        else        {g2[e2]=gg;atomicAdd(deg2+c_,gg);}
                    }
                }
            }
        }
    }
}

__global__ void rsqrt_kernel(float*d1,float*d2,int n){
    int i=blockIdx.x*blockDim.x+threadIdx.x;
    if(i<n){d1[i]=rsqrtf(d1[i]);d2[i]=rsqrtf(d2[i]);}
}

__global__ void scan_block_sums(const int* __restrict__ cnt,int* __restrict__ bsums,int n){
    __shared__ int wsum[32];
    int i=blockIdx.x*1024+threadIdx.x;
    int v=(i<n)?cnt[i]:0;
    #pragma unroll
    for(int o=16;o;o>>=1) v+=__shfl_down_sync(0xffffffffu,v,o);
    if((threadIdx.x&31)==0) wsum[threadIdx.x>>5]=v;
    __syncthreads();
    if(threadIdx.x<32){
        int s=wsum[threadIdx.x];
        #pragma unroll
        for(int o=16;o;o>>=1) s+=__shfl_down_sync(0xffffffffu,s,o);
        if(threadIdx.x==0) bsums[blockIdx.x]=s;
    }
}
__global__ void scan_bsums_excl(int*bsums,int nb){
    if(threadIdx.x==0&&blockIdx.x==0){
        int acc=0;
        for(int i=0;i<nb;i++){int t=bsums[i];bsums[i]=acc;acc+=t;}
    }
}
__global__ void scan_final(const int* __restrict__ cnt,const int* __restrict__ bsums,
                           int* __restrict__ base,int n){
    __shared__ int wsum[32];
    int i=blockIdx.x*1024+threadIdx.x;
    int v=(i<n)?cnt[i]:0;
    int lane=threadIdx.x&31,w=threadIdx.x>>5;
    int incl=v;
    #pragma unroll
    for(int o=1;o<32;o<<=1){int t=__shfl_up_sync(0xffffffffu,incl,o);if(lane>=o)incl+=t;}
    if(lane==31) wsum[w]=incl;
    __syncthreads();
    if(w==0){
        int s=wsum[lane];
        #pragma unroll
        for(int o=1;o<32;o<<=1){int t=__shfl_up_sync(0xffffffffu,s,o);if(lane>=o)s+=t;}
        __syncwarp();
        wsum[lane]=s;
    }
    __syncthreads();
    int prev=(w==0)?0:wsum[w-1];
    if(i<n) base[i]=incl-v+prev+bsums[blockIdx.x];
}

__global__ void place_kernel(const int* __restrict__ rows,const int* __restrict__ cols,
    const float* __restrict__ g1,const float* __restrict__ g2,
    const float* __restrict__ d1,const float* __restrict__ d2,
    const int* __restrict__ base,int* __restrict__ cur,float4* __restrict__ edges,int E)
{
    int e=blockIdx.x*blockDim.x+threadIdx.x;
    if(e>=E) return;
    int r=__ldg(rows+e),c=__ldg(cols+e);
    int slot=__ldg(base+c)+atomicAdd(cur+c,1);
    float4 rec;
    rec.x=__int_as_float(r);
    rec.y=__ldg(g1+e)*__ldg(d1+r)*__ldg(d1+c);
    rec.z=__ldg(g2+e)*__ldg(d2+r)*__ldg(d2+c);
    rec.w=0.0f;
    edges[slot]=rec;
}

__global__ void __launch_bounds__(256) gemm128_kernel(
    const float* __restrict__ X,const float* __restrict__ W,
    float* __restrict__ out,int n,int relu_in)
{
    __shared__ __align__(16) u64 xs[32*128];
    int warp=threadIdx.x>>5,lane=threadIdx.x&31;
    for(int base=blockIdx.x*32;base<n;base+=gridDim.x*32){
        int r0=base+warp*4;
        #pragma unroll
        for(int i=0;i<4;i++){
            int r=r0+i;
            float4 v=make_float4(0.f,0.f,0.f,0.f);
            if(r<n) v=((const float4*)(X+(size_t)r*128))[lane];
            if(relu_in){v.x=fmaxf(v.x,0.f);v.y=fmaxf(v.y,0.f);v.z=fmaxf(v.z,0.f);v.w=fmaxf(v.w,0.f);}
            u64* dst=xs+(warp*4+i)*128+lane*4;
            dst[0]=bcast2(v.x);dst[1]=bcast2(v.y);dst[2]=bcast2(v.z);dst[3]=bcast2(v.w);
        }
        __syncwarp();
        u64 a0x=0,a0y=0,a1x=0,a1y=0,a2x=0,a2y=0,a3x=0,a3y=0;
        const u64* x0=xs+warp*4*128;
        #pragma unroll 8
        for(int k=0;k<128;k++){
            ulonglong2 w=__ldg((const ulonglong2*)(W+k*128)+lane);
            u64 xa=x0[k],xb=x0[128+k],xc=x0[256+k],xd=x0[384+k];
            ffma2(a0x,xa,w.x);ffma2(a0y,xa,w.y);
            ffma2(a1x,xb,w.x);ffma2(a1y,xb,w.y);
            ffma2(a2x,xc,w.x);ffma2(a2y,xc,w.y);
            ffma2(a3x,xd,w.x);ffma2(a3y,xd,w.y);
        }
        if(r0+0<n) ((ulonglong2*)(out+(size_t)(r0+0)*128))[lane]=make_ulonglong2(a0x,a0y);
        if(r0+1<n) ((ulonglong2*)(out+(size_t)(r0+1)*128))[lane]=make_ulonglong2(a1x,a1y);
        if(r0+2<n) ((ulonglong2*)(out+(size_t)(r0+2)*128))[lane]=make_ulonglong2(a2x,a2y);
        if(r0+3<n) ((ulonglong2*)(out+(size_t)(r0+3)*128))[lane]=make_ulonglong2(a3x,a3y);
        __syncwarp();
    }
}

__global__ void __launch_bounds__(256)
gather_kernel(const float* __restrict__ h,const float* __restrict__ dinv,
              const int* __restrict__ base,const int* __restrict__ cnt,
              const float4* __restrict__ edges,float* __restrict__ out,int n,int sel)
{
    int node=blockIdx.x*(blockDim.x>>5)+(threadIdx.x>>5);
    if(node>=n) return;
    int lane=threadIdx.x&31;
    float di=__ldg(dinv+node);
    float w0=di*di;
    float4 acc=__ldg((const float4*)(h+(size_t)node*128)+lane);
    acc.x*=w0;acc.y*=w0;acc.z*=w0;acc.w*=w0;
    int s=__ldg(base+node);
    int end=s+__ldg(cnt+node);
    for(;s+4<=end;s+=4){
        float4 e0=__ldg(edges+s),e1=__ldg(edges+s+1),e2=__ldg(edges+s+2),e3=__ldg(edges+s+3);
        int r0=__float_as_int(e0.x),r1=__float_as_int(e1.x),r2=__float_as_int(e2.x),r3=__float_as_int(e3.x);
        float w0_=sel?e0.z:e0.y,w1_=sel?e1.z:e1.y,w2_=sel?e2.z:e2.y,w3_=sel?e3.z:e3.y;
        float4 v0=__ldg((const float4*)(h+(size_t)r0*128)+lane);
        float4 v1=__ldg((const float4*)(h+(size_t)r1*128)+lane);
        float4 v2=__ldg((const float4*)(h+(size_t)r2*128)+lane);
        float4 v3=__ldg((const float4*)(h+(size_t)r3*128)+lane);
        acc.x=fmaf(w0_,v0.x,acc.x);acc.y=fmaf(w0_,v0.y,acc.y);acc.z=fmaf(w0_,v0.z,acc.z);acc.w=fmaf(w0_,v0.w,acc.w);
        acc.x=fmaf(w1_,v1.x,acc.x);acc.y=fmaf(w1_,v1.y,acc.y);acc.z=fmaf(w1_,v1.z,acc.z);acc.w=fmaf(w1_,v1.w,acc.w);
        acc.x=fmaf(w2_,v2.x,acc.x);acc.y=fmaf(w2_,v2.y,acc.y);acc.z=fmaf(w2_,v2.z,acc.z);acc.w=fmaf(w2_,v2.w,acc.w);
        acc.x=fmaf(w3_,v3.x,acc.x);acc.y=fmaf(w3_,v3.y,acc.y);acc.z=fmaf(w3_,v3.z,acc.z);acc.w=fmaf(w3_,v3.w,acc.w);
    }
    for(;s<end;s++){
        float4 e0=__ldg(edges+s);
        int r0=__float_as_int(e0.x);
        float wa=sel?e0.z:e0.y;
        float4 v0=__ldg((const float4*)(h+(size_t)r0*128)+lane);
        acc.x=fmaf(wa,v0.x,acc.x);acc.y=fmaf(wa,v0.y,acc.y);acc.z=fmaf(wa,v0.z,acc.z);acc.w=fmaf(wa,v0.w,acc.w);
    }
    ((float4*)(out+(size_t)node*128))[lane]=acc;
}

extern "C" void kernel_launch(void* const* d_in,const int* in_sizes,int n_in,
                              void* d_out,int out_size)
{
    const float* x=(const float*)d_in[0];
    const int*   ei=(const int*)d_in[1];
    const float* ea=(const float*)d_in[2];
    const float* W1=(const float*)d_in[3];
    const float* m1w1=(const float*)d_in[4];
    const float* m1b1=(const float*)d_in[5];
    const float* m1w2=(const float*)d_in[6];
    const float* m1b2=(const float*)d_in[7];
    const float* W2=(const float*)d_in[8];
    const float* m2w1=(const float*)d_in[9];
    const float* m2b1=(const float*)d_in[10];
    const float* m2w2=(const float*)d_in[11];
    const float* m2b2=(const float*)d_in[12];
    float* out=(float*)d_out;

    int n=in_sizes[0]/128;
    int E=in_sizes[1]/2;
    const int* rows=ei;
    const int* cols=ei+E;
    int nblk=(n+1023)/1024;

    float *ph,*pagg,*pg1,*pg2,*pd1,*pd2;
    float4* pedges;
    int *pcnt,*pcur,*pbase,*pbsums;
    cudaGetSymbolAddress((void**)&ph,g_h);
    cudaGetSymbolAddress((void**)&pagg,g_agg);
    cudaGetSymbolAddress((void**)&pg1,g_g1);
    cudaGetSymbolAddress((void**)&pg2,g_g2);
    cudaGetSymbolAddress((void**)&pd1,g_d1);
    cudaGetSymbolAddress((void**)&pd2,g_d2);
    cudaGetSymbolAddress((void**)&pcnt,g_cnt);
    cudaGetSymbolAddress((void**)&pcur,g_cur);
    cudaGetSymbolAddress((void**)&pbase,g_base);
    cudaGetSymbolAddress((void**)&pbsums,g_bsums);
    cudaGetSymbolAddress((void**)&pedges,g_edges);

    const int GATE_SMEM=(2*48*136+512)*4;   // 54272 B
    cudaFuncSetAttribute(gate_mma_kernel,cudaFuncAttributeMaxDynamicSharedMemorySize,GATE_SMEM);

    init_kernel<<<(n+255)/256,256>>>(pd1,pd2,pcnt,pcur,n);
    gate_mma_kernel<<<296,256,GATE_SMEM>>>(ea,m1w1,m1b1,m1w2,m1b2,m2w1,m2b1,m2w2,m2b2,
                                           cols,pg1,pg2,pd1,pd2,pcnt,E);
    rsqrt_kernel<<<(n+255)/256,256>>>(pd1,pd2,n);

    scan_block_sums<<<nblk,1024>>>(pcnt,pbsums,n);
    scan_bsums_excl<<<1,32>>>(pbsums,nblk);
    scan_final<<<nblk,1024>>>(pcnt,pbsums,pbase,n);
    place_kernel<<<(E+255)/256,256>>>(rows,cols,pg1,pg2,pd1,pd2,pbase,pcur,pedges,E);

    gemm128_kernel<<<592,256>>>(x,W1,ph,n,0);
    gather_kernel<<<(n+7)/8,256>>>(ph,pd1,pbase,pcnt,pedges,pagg,n,0);

    gemm128_kernel<<<592,256>>>(pagg,W2,ph,n,1);
    gather_kernel<<<(n+7)/8,256>>>(ph,pd2,pbase,pcnt,pedges,out,n,1);
}

// round 8
// speedup vs baseline: 1.3689x; 1.0840x over previous
#include <cuda_runtime.h>
#include <math.h>
#include <cstdint>

#define MAXN 100000
#define MAXE 1600000
#define NBLK 98
typedef unsigned long long u64;

__device__ __forceinline__ float tf32_hi(float x){return __uint_as_float(__float_as_uint(x)&0xffffe000u);}

// m16n8k8 tf32 mma (sm_80+ PTX)
__device__ __forceinline__ void mma8(float* c,const uint32_t* a,uint32_t b0,uint32_t b1){
    asm volatile("mma.sync.aligned.m16n8k8.row.col.f32.tf32.tf32.f32 "
                 "{%0,%1,%2,%3},{%4,%5,%6,%7},{%8,%9},{%0,%1,%2,%3};"
        :"+f"(c[0]),"+f"(c[1]),"+f"(c[2]),"+f"(c[3])
        :"r"(a[0]),"r"(a[1]),"r"(a[2]),"r"(a[3]),"r"(b0),"r"(b1));
}

__device__ float  g_h[(size_t)MAXN*128];
__device__ float  g_agg[(size_t)MAXN*128];
__device__ float  g_g1[MAXE];
__device__ float  g_g2[MAXE];
__device__ float  g_d1[MAXN];
__device__ float  g_d2[MAXN];
__device__ int    g_cnt[MAXN];
__device__ int    g_cur[MAXN];
__device__ int    g_base[MAXN];
__device__ int    g_bsums[NBLK+1];
__device__ float4 g_edges[MAXE];

__global__ void init_kernel(float*d1,float*d2,int*cnt,int*cur,int n){
    int i=blockIdx.x*blockDim.x+threadIdx.x;
    if(i<n){d1[i]=1.0f;d2[i]=1.0f;cnt[i]=0;cur[i]=0;}
}

// ---------------------------------------------------------------------------
// Tensor-core gate (unchanged from R7): split-fp32 tf32, K=48, bias in C-init.
__global__ void __launch_bounds__(256) gate_mma_kernel(
    const float* __restrict__ ea,
    const float* __restrict__ m1w1,const float* __restrict__ m1b1,
    const float* __restrict__ m1w2,const float* __restrict__ m1b2,
    const float* __restrict__ m2w1,const float* __restrict__ m2b1,
    const float* __restrict__ m2w2,const float* __restrict__ m2b2,
    const int* __restrict__ cols,
    float* __restrict__ g1,float* __restrict__ g2,
    float* __restrict__ deg1,float* __restrict__ deg2,int* __restrict__ cnt,int E)
{
    extern __shared__ float ds[];
    float* biasp=ds+2*48*136;
    float* w2p  =biasp+256;
    int tid=threadIdx.x;

    for(int idx=tid;idx<2*48*128;idx+=256){
        int layer=idx/6144,rem=idx%6144,k=rem>>7,n=rem&127;
        const float* W=layer?m2w1:m1w1;
        float v;
        if(k<16)      v=tf32_hi(__ldg(W+k*128+n));
        else if(k<32) v=tf32_hi(__ldg(W+(k-16)*128+n));
        else          {float w=__ldg(W+(k-32)*128+n);v=w-tf32_hi(w);}
        ds[layer*6528+k*136+n]=v;
    }
    if(tid<256){
        biasp[tid]=(tid<128)?__ldg(m1b1+tid):__ldg(m2b1+tid-128);
        w2p[tid]  =(tid<128)?__ldg(m1w2+tid):__ldg(m2w2+tid-128);
    }
    __syncthreads();

    int lane=tid&31,g=lane>>2,t=lane&3;
    int w=blockIdx.x*(blockDim.x>>5)+(tid>>5);
    int nwarps=gridDim.x*(blockDim.x>>5);
    int ntask=(E+63)>>6;
    float b2v[2]={__ldg(m1b2),__ldg(m2b2)};

    for(int task=w;task<ntask;task+=nwarps){
        int e0=task*64;
        uint32_t Ahi[4][8],Alo[4][8];
        #pragma unroll
        for(int mt=0;mt<4;mt++){
            int r1=e0+mt*16+g,r2=r1+8;
            #pragma unroll
            for(int j=0;j<4;j++){
                int ac=(j&1)*4+(j>>1)*8+t;
                int fi=(j>>1)*4+(j&1)*2;
                float v1=(r1<E)?__ldg(ea+(size_t)r1*16+ac):0.f;
                float v2=(r2<E)?__ldg(ea+(size_t)r2*16+ac):0.f;
                uint32_t h1=__float_as_uint(v1)&0xffffe000u;
                uint32_t h2=__float_as_uint(v2)&0xffffe000u;
                Ahi[mt][fi]=h1;  Ahi[mt][fi+1]=h2;
                Alo[mt][fi]=__float_as_uint(v1-__uint_as_float(h1));
                Alo[mt][fi+1]=__float_as_uint(v2-__uint_as_float(h2));
            }
        }
        #pragma unroll
        for(int layer=0;layer<2;layer++){
            const float* Bl=ds+layer*6528;
            const float* biasl=biasp+layer*128;
            const float* w2l=w2p+layer*128;
            float p0[4]={0,0,0,0},p1[4]={0,0,0,0};
            #pragma unroll 1
            for(int nt=0;nt<16;nt++){
                int n0=nt*8;
                float bA=biasl[n0+2*t],bB=biasl[n0+2*t+1];
                float c[4][4];
                #pragma unroll
                for(int mt=0;mt<4;mt++){c[mt][0]=bA;c[mt][1]=bB;c[mt][2]=bA;c[mt][3]=bB;}
                #define STEP(AARR,OFF,K0) do{                                   \
                    uint32_t b0=__float_as_uint(Bl[(K0+t)*136+n0+g]);           \
                    uint32_t b1v=__float_as_uint(Bl[(K0+t+4)*136+n0+g]);        \
                    _Pragma("unroll")                                           \
                    for(int mt=0;mt<4;mt++) mma8(c[mt],&AARR[mt][OFF],b0,b1v);  \
                }while(0)
                STEP(Ahi,0,0);  STEP(Ahi,4,8);
                STEP(Alo,0,16); STEP(Alo,4,24);
                STEP(Ahi,0,32); STEP(Ahi,4,40);
                #undef STEP
                float wA=w2l[n0+2*t],wB=w2l[n0+2*t+1];
                #pragma unroll
                for(int mt=0;mt<4;mt++){
                    p0[mt]+=fmaxf(c[mt][0],0.f)*wA+fmaxf(c[mt][1],0.f)*wB;
                    p1[mt]+=fmaxf(c[mt][2],0.f)*wA+fmaxf(c[mt][3],0.f)*wB;
                }
            }
            #pragma unroll
            for(int mt=0;mt<4;mt++){
                p0[mt]+=__shfl_xor_sync(0xffffffffu,p0[mt],1);
                p0[mt]+=__shfl_xor_sync(0xffffffffu,p0[mt],2);
                p1[mt]+=__shfl_xor_sync(0xffffffffu,p1[mt],1);
                p1[mt]+=__shfl_xor_sync(0xffffffffu,p1[mt],2);
            }
            if(t==0){
                float b2=b2v[layer];
                #pragma unroll
                for(int mt=0;mt<4;mt++){
                    int e=e0+mt*16+g;
                    if(e<E){
                        float gg=1.0f/(1.0f+expf(-(p0[mt]+b2)));
                        int c_=__ldg(cols+e);
                        if(layer==0){g1[e]=gg;atomicAdd(deg1+c_,gg);atomicAdd(cnt+c_,1);}
                        else        {g2[e]=gg;atomicAdd(deg2+c_,gg);}
                    }
                    int e2=e0+mt*16+g+8;
                    if(e2<E){
                        float gg=1.0f/(1.0f+expf(-(p1[mt]+b2)));
                        int c_=__ldg(cols+e2);
                        if(layer==0){g1[e2]=gg;atomicAdd(deg1+c_,gg);atomicAdd(cnt+c_,1);}
                        else        {g2[e2]=gg;atomicAdd(deg2+c_,gg);}
                    }
                }
            }
        }
    }
}

// ---------------------------------------------------------------------------
// Dense GEMM via mma.sync tf32 split-fp32 (3 terms). Per warp: 16 rows x 128
// cols; W fp32 in shared (stride 136, conflict-free), hi/lo derived at frag
// load; X staged per-warp fp32 (stride 132, conflict-free); C -> float2 STG.
__global__ void __launch_bounds__(256) gemm_mma_kernel(
    const float* __restrict__ X,const float* __restrict__ W,
    float* __restrict__ out,int n,int relu_in)
{
    extern __shared__ float sm[];
    float* Ws=sm;                 // 128*136
    float* Xs=sm+128*136;         // 8 warps * 16*132
    int tid=threadIdx.x,wid=tid>>5,lane=tid&31;
    int g=lane>>2,t=lane&3;

    for(int idx=tid;idx<128*32;idx+=256){
        int k=idx>>5,nn=(idx&31)*4;
        float4 v=__ldg((const float4*)(W+k*128+nn));
        float* d=Ws+k*136+nn;
        d[0]=v.x;d[1]=v.y;d[2]=v.z;d[3]=v.w;
    }
    __syncthreads();

    float* Xw=Xs+wid*(16*132);
    int ntiles=(n+127)>>7;
    for(int tile=blockIdx.x;tile<ntiles;tile+=gridDim.x){
        int r0=tile*128+wid*16;
        #pragma unroll 4
        for(int i=0;i<16;i++){
            int r=r0+i;
            float4 v=make_float4(0.f,0.f,0.f,0.f);
            if(r<n) v=__ldg((const float4*)(X+(size_t)r*128)+lane);
            if(relu_in){v.x=fmaxf(v.x,0.f);v.y=fmaxf(v.y,0.f);v.z=fmaxf(v.z,0.f);v.w=fmaxf(v.w,0.f);}
            float* d=Xw+i*132+lane*4;
            d[0]=v.x;d[1]=v.y;d[2]=v.z;d[3]=v.w;
        }
        __syncwarp();

        float c[16][4];
        #pragma unroll
        for(int nf=0;nf<16;nf++){c[nf][0]=0.f;c[nf][1]=0.f;c[nf][2]=0.f;c[nf][3]=0.f;}

        #pragma unroll 1
        for(int ks=0;ks<16;ks++){
            int k0=ks*8;
            float x0=Xw[g*132+k0+t],x1=Xw[(g+8)*132+k0+t];
            float x2=Xw[g*132+k0+t+4],x3=Xw[(g+8)*132+k0+t+4];
            uint32_t ahi[4],alo[4];
            ahi[0]=__float_as_uint(x0)&0xffffe000u; alo[0]=__float_as_uint(x0-__uint_as_float(ahi[0]));
            ahi[1]=__float_as_uint(x1)&0xffffe000u; alo[1]=__float_as_uint(x1-__uint_as_float(ahi[1]));
            ahi[2]=__float_as_uint(x2)&0xffffe000u; alo[2]=__float_as_uint(x2-__uint_as_float(ahi[2]));
            ahi[3]=__float_as_uint(x3)&0xffffe000u; alo[3]=__float_as_uint(x3-__uint_as_float(ahi[3]));
            #pragma unroll
            for(int nf=0;nf<16;nf++){
                int n0=nf*8;
                float b0r=Ws[(k0+t)*136+n0+g],b1r=Ws[(k0+t+4)*136+n0+g];
                uint32_t bh0=__float_as_uint(b0r)&0xffffe000u;
                uint32_t bh1=__float_as_uint(b1r)&0xffffe000u;
                uint32_t bl0=__float_as_uint(b0r-__uint_as_float(bh0));
                uint32_t bl1=__float_as_uint(b1r-__uint_as_float(bh1));
                mma8(c[nf],ahi,bh0,bh1);
                mma8(c[nf],alo,bh0,bh1);
                mma8(c[nf],ahi,bl0,bl1);
            }
        }

        int ra=r0+g,rb=r0+g+8;
        #pragma unroll
        for(int nf=0;nf<16;nf++){
            int col=nf*8+2*t;
            if(ra<n) *(float2*)(out+(size_t)ra*128+col)=make_float2(c[nf][0],c[nf][1]);
            if(rb<n) *(float2*)(out+(size_t)rb*128+col)=make_float2(c[nf][2],c[nf][3]);
        }
        __syncwarp();
    }
}

__global__ void rsqrt_kernel(float*d1,float*d2,int n){
    int i=blockIdx.x*blockDim.x+threadIdx.x;
    if(i<n){d1[i]=rsqrtf(d1[i]);d2[i]=rsqrtf(d2[i]);}
}

__global__ void scan_block_sums(const int* __restrict__ cnt,int* __restrict__ bsums,int n){
    __shared__ int wsum[32];
    int i=blockIdx.x*1024+threadIdx.x;
    int v=(i<n)?cnt[i]:0;
    #pragma unroll
    for(int o=16;o;o>>=1) v+=__shfl_down_sync(0xffffffffu,v,o);
    if((threadIdx.x&31)==0) wsum[threadIdx.x>>5]=v;
    __syncthreads();
    if(threadIdx.x<32){
        int s=wsum[threadIdx.x];
        #pragma unroll
        for(int o=16;o;o>>=1) s+=__shfl_down_sync(0xffffffffu,s,o);
        if(threadIdx.x==0) bsums[blockIdx.x]=s;
    }
}
__global__ void scan_bsums_excl(int*bsums,int nb){
    if(threadIdx.x==0&&blockIdx.x==0){
        int acc=0;
        for(int i=0;i<nb;i++){int t=bsums[i];bsums[i]=acc;acc+=t;}
    }
}
__global__ void scan_final(const int* __restrict__ cnt,const int* __restrict__ bsums,
                           int* __restrict__ base,int n){
    __shared__ int wsum[32];
    int i=blockIdx.x*1024+threadIdx.x;
    int v=(i<n)?cnt[i]:0;
    int lane=threadIdx.x&31,w=threadIdx.x>>5;
    int incl=v;
    #pragma unroll
    for(int o=1;o<32;o<<=1){int t=__shfl_up_sync(0xffffffffu,incl,o);if(lane>=o)incl+=t;}
    if(lane==31) wsum[w]=incl;
    __syncthreads();
    if(w==0){
        int s=wsum[lane];
        #pragma unroll
        for(int o=1;o<32;o<<=1){int t=__shfl_up_sync(0xffffffffu,s,o);if(lane>=o)s+=t;}
        __syncwarp();
        wsum[lane]=s;
    }
    __syncthreads();
    int prev=(w==0)?0:wsum[w-1];
    if(i<n) base[i]=incl-v+prev+bsums[blockIdx.x];
}

__global__ void place_kernel(const int* __restrict__ rows,const int* __restrict__ cols,
    const float* __restrict__ g1,const float* __restrict__ g2,
    const float* __restrict__ d1,const float* __restrict__ d2,
    const int* __restrict__ base,int* __restrict__ cur,float4* __restrict__ edges,int E)
{
    int e=blockIdx.x*blockDim.x+threadIdx.x;
    if(e>=E) return;
    int r=__ldg(rows+e),c=__ldg(cols+e);
    int slot=__ldg(base+c)+atomicAdd(cur+c,1);
    float4 rec;
    rec.x=__int_as_float(r);
    rec.y=__ldg(g1+e)*__ldg(d1+r)*__ldg(d1+c);
    rec.z=__ldg(g2+e)*__ldg(d2+r)*__ldg(d2+c);
    rec.w=0.0f;
    edges[slot]=rec;
}

__global__ void __launch_bounds__(256)
gather_kernel(const float* __restrict__ h,const float* __restrict__ dinv,
              const int* __restrict__ base,const int* __restrict__ cnt,
              const float4* __restrict__ edges,float* __restrict__ out,int n,int sel)
{
    int node=blockIdx.x*(blockDim.x>>5)+(threadIdx.x>>5);
    if(node>=n) return;
    int lane=threadIdx.x&31;
    float di=__ldg(dinv+node);
    float w0=di*di;
    float4 acc=__ldg((const float4*)(h+(size_t)node*128)+lane);
    acc.x*=w0;acc.y*=w0;acc.z*=w0;acc.w*=w0;
    int s=__ldg(base+node);
    int end=s+__ldg(cnt+node);
    for(;s+4<=end;s+=4){
        float4 e0=__ldg(edges+s),e1=__ldg(edges+s+1),e2=__ldg(edges+s+2),e3=__ldg(edges+s+3);
        int r0=__float_as_int(e0.x),r1=__float_as_int(e1.x),r2=__float_as_int(e2.x),r3=__float_as_int(e3.x);
        float w0_=sel?e0.z:e0.y,w1_=sel?e1.z:e1.y,w2_=sel?e2.z:e2.y,w3_=sel?e3.z:e3.y;
        float4 v0=__ldg((const float4*)(h+(size_t)r0*128)+lane);
        float4 v1=__ldg((const float4*)(h+(size_t)r1*128)+lane);
        float4 v2=__ldg((const float4*)(h+(size_t)r2*128)+lane);
        float4 v3=__ldg((const float4*)(h+(size_t)r3*128)+lane);
        acc.x=fmaf(w0_,v0.x,acc.x);acc.y=fmaf(w0_,v0.y,acc.y);acc.z=fmaf(w0_,v0.z,acc.z);acc.w=fmaf(w0_,v0.w,acc.w);
        acc.x=fmaf(w1_,v1.x,acc.x);acc.y=fmaf(w1_,v1.y,acc.y);acc.z=fmaf(w1_,v1.z,acc.z);acc.w=fmaf(w1_,v1.w,acc.w);
        acc.x=fmaf(w2_,v2.x,acc.x);acc.y=fmaf(w2_,v2.y,acc.y);acc.z=fmaf(w2_,v2.z,acc.z);acc.w=fmaf(w2_,v2.w,acc.w);
        acc.x=fmaf(w3_,v3.x,acc.x);acc.y=fmaf(w3_,v3.y,acc.y);acc.z=fmaf(w3_,v3.z,acc.z);acc.w=fmaf(w3_,v3.w,acc.w);
    }
    for(;s<end;s++){
        float4 e0=__ldg(edges+s);
        int r0=__float_as_int(e0.x);
        float wa=sel?e0.z:e0.y;
        float4 v0=__ldg((const float4*)(h+(size_t)r0*128)+lane);
        acc.x=fmaf(wa,v0.x,acc.x);acc.y=fmaf(wa,v0.y,acc.y);acc.z=fmaf(wa,v0.z,acc.z);acc.w=fmaf(wa,v0.w,acc.w);
    }
    ((float4*)(out+(size_t)node*128))[lane]=acc;
}

extern "C" void kernel_launch(void* const* d_in,const int* in_sizes,int n_in,
                              void* d_out,int out_size)
{
    const float* x=(const float*)d_in[0];
    const int*   ei=(const int*)d_in[1];
    const float* ea=(const float*)d_in[2];
    const float* W1=(const float*)d_in[3];
    const float* m1w1=(const float*)d_in[4];
    const float* m1b1=(const float*)d_in[5];
    const float* m1w2=(const float*)d_in[6];
    const float* m1b2=(const float*)d_in[7];
    const float* W2=(const float*)d_in[8];
    const float* m2w1=(const float*)d_in[9];
    const float* m2b1=(const float*)d_in[10];
    const float* m2w2=(const float*)d_in[11];
    const float* m2b2=(const float*)d_in[12];
    float* out=(float*)d_out;

    int n=in_sizes[0]/128;
    int E=in_sizes[1]/2;
    const int* rows=ei;
    const int* cols=ei+E;
    int nblk=(n+1023)/1024;

    float *ph,*pagg,*pg1,*pg2,*pd1,*pd2;
    float4* pedges;
    int *pcnt,*pcur,*pbase,*pbsums;
    cudaGetSymbolAddress((void**)&ph,g_h);
    cudaGetSymbolAddress((void**)&pagg,g_agg);
    cudaGetSymbolAddress((void**)&pg1,g_g1);
    cudaGetSymbolAddress((void**)&pg2,g_g2);
    cudaGetSymbolAddress((void**)&pd1,g_d1);
    cudaGetSymbolAddress((void**)&pd2,g_d2);
    cudaGetSymbolAddress((void**)&pcnt,g_cnt);
    cudaGetSymbolAddress((void**)&pcur,g_cur);
    cudaGetSymbolAddress((void**)&pbase,g_base);
    cudaGetSymbolAddress((void**)&pbsums,g_bsums);
    cudaGetSymbolAddress((void**)&pedges,g_edges);

    const int GATE_SMEM=(2*48*136+512)*4;        // 54272 B
    const int GEMM_SMEM=(128*136+8*16*132)*4;    // 137216 B
    cudaFuncSetAttribute(gate_mma_kernel,cudaFuncAttributeMaxDynamicSharedMemorySize,GATE_SMEM);
    cudaFuncSetAttribute(gemm_mma_kernel,cudaFuncAttributeMaxDynamicSharedMemorySize,GEMM_SMEM);

    init_kernel<<<(n+255)/256,256>>>(pd1,pd2,pcnt,pcur,n);
    gate_mma_kernel<<<296,256,GATE_SMEM>>>(ea,m1w1,m1b1,m1w2,m1b2,m2w1,m2b1,m2w2,m2b2,
                                           cols,pg1,pg2,pd1,pd2,pcnt,E);
    rsqrt_kernel<<<(n+255)/256,256>>>(pd1,pd2,n);

    scan_block_sums<<<nblk,1024>>>(pcnt,pbsums,n);
    scan_bsums_excl<<<1,32>>>(pbsums,nblk);
    scan_final<<<nblk,1024>>>(pcnt,pbsums,pbase,n);
    place_kernel<<<(E+255)/256,256>>>(rows,cols,pg1,pg2,pd1,pd2,pbase,pcur,pedges,E);

    gemm_mma_kernel<<<148,256,GEMM_SMEM>>>(x,W1,ph,n,0);
    gather_kernel<<<(n+7)/8,256>>>(ph,pd1,pbase,pcnt,pedges,pagg,n,0);

    gemm_mma_kernel<<<148,256,GEMM_SMEM>>>(pagg,W2,ph,n,1);
    gather_kernel<<<(n+7)/8,256>>>(ph,pd2,pbase,pcnt,pedges,out,n,1);
}